// round 16
// baseline (speedup 1.0000x reference)
#include <cuda_runtime.h>
#include <cstdint>

#define NB  32
#define NC  192
#define NL  4096
#define CPB 2                  // channels per block
#define NCB (NC / CPB)         // 96 blocks per batch
#define GBLK (NB * NCB)        // 3072 blocks
#define GT  512                // threads per block

// Scratch (no dynamic allocation; zero-initialized at load)
__device__ int   g_order[NB * NL];   // always-valid token ids 0..NL-1
__device__ int   g_count[NB];
__device__ float g_theta[NB];
__device__ int   g_ready[NB];        // per-batch release flag  (reset per run)
__device__ int   g_bdone[NB];        // per-batch done tickets  (reset per run)
__device__ int   g_sticket;          // scalars-kernel ticket   (reset per run)
__device__ int   g_scnt[NB];
__device__ float g_sth[NB];

__device__ __forceinline__ void pdl_trigger() {
    asm volatile("griddepcontrol.launch_dependents;" ::: "memory");
}

// ---------------------------------------------------------------------------
// Fused gather kernel. Block blk handles batch b = blk/NCB, channels
// c0..c0+1. The FIRST block of each batch group (blk % NCB == 0) computes
// that batch's stats + compaction order, then releases g_ready[b]. All
// blocks stage x to SMEM first (DRAM busy during stats), spin only on their
// own batch's flag, gather, and the last consumer of each batch resets the
// batch's flags (replay-safe, no hot single-address atomic).
// ---------------------------------------------------------------------------
__global__ __launch_bounds__(GT, 4) void fused_kernel(const float* __restrict__ x,
                                                      const float* __restrict__ delta,
                                                      float* __restrict__ y)
{
    __shared__ float  sx[CPB * NL];          // 32 KB
    __shared__ float  smn[16], smx[16];
    __shared__ double ssum[16], ssq[16];
    __shared__ int    wsum[16];
    __shared__ float  s_lo, s_rng, s_theta;

    const int blk  = blockIdx.x;
    const int tid  = threadIdx.x;
    const int lane = tid & 31;
    const int warp = tid >> 5;               // 16 warps
    const int b    = blk / NCB;
    const int c0   = (blk % NCB) * CPB;
    const size_t base = ((size_t)b * NC + c0) * NL;
    const bool producer = ((blk % NCB) == 0);

    // ---- Producer: stats + compaction for batch b ----
    if (producer) {
        const float4* dp = reinterpret_cast<const float4*>(delta + (size_t)b * NL) + tid * 2;
        float4 d0 = dp[0], d1 = dp[1];
        float a[8] = { fabsf(d0.x), fabsf(d0.y), fabsf(d0.z), fabsf(d0.w),
                       fabsf(d1.x), fabsf(d1.y), fabsf(d1.z), fabsf(d1.w) };

        float mn = a[0], mx = a[0];
        double s0 = 0.0, s1 = 0.0, q0 = 0.0, q1 = 0.0;
        #pragma unroll
        for (int i = 0; i < 4; i++) {
            mn = fminf(mn, fminf(a[2*i], a[2*i+1]));
            mx = fmaxf(mx, fmaxf(a[2*i], a[2*i+1]));
            double e0 = (double)a[2*i], e1 = (double)a[2*i+1];
            s0 += e0; q0 += e0 * e0;
            s1 += e1; q1 += e1 * e1;
        }
        double s = s0 + s1, q = q0 + q1;

        #pragma unroll
        for (int o = 16; o; o >>= 1) {
            mn = fminf(mn, __shfl_xor_sync(0xffffffffu, mn, o));
            mx = fmaxf(mx, __shfl_xor_sync(0xffffffffu, mx, o));
            s += __shfl_xor_sync(0xffffffffu, s, o);
            q += __shfl_xor_sync(0xffffffffu, q, o);
        }
        if (lane == 0) { smn[warp] = mn; smx[warp] = mx; ssum[warp] = s; ssq[warp] = q; }
        __syncthreads();

        if (warp == 0) {
            mn = (lane < 16) ? smn[lane] :  1e30f;
            mx = (lane < 16) ? smx[lane] : -1e30f;
            s  = (lane < 16) ? ssum[lane] : 0.0;
            q  = (lane < 16) ? ssq[lane]  : 0.0;
            #pragma unroll
            for (int o = 8; o; o >>= 1) {
                mn = fminf(mn, __shfl_xor_sync(0xffffffffu, mn, o));
                mx = fmaxf(mx, __shfl_xor_sync(0xffffffffu, mx, o));
                s += __shfl_xor_sync(0xffffffffu, s, o);
                q += __shfl_xor_sync(0xffffffffu, q, o);
            }
            if (lane == 0) {
                float lo  = mn;
                float rng = fmaxf(mx - lo, 1e-3f);
                double mu_a  = s / (double)NL;
                double var_a = (q - s * s / (double)NL) / (double)(NL - 1);
                if (var_a < 0.0) var_a = 0.0;
                s_lo = lo; s_rng = rng;
                s_theta = (float)((mu_a - (double)lo) / (double)rng
                                  - 0.1 * sqrt(var_a) / (double)rng);
            }
        }
        __syncthreads();

        const float lo = s_lo, rng = s_rng, theta = s_theta;
        unsigned kbits = 0;
        int local = 0;
        #pragma unroll
        for (int i = 0; i < 8; i++) {
            float imp = (a[i] - lo) / rng;
            if (imp >= theta) { kbits |= (1u << i); local++; }
        }

        int incl = local;
        #pragma unroll
        for (int o = 1; o < 32; o <<= 1) {
            int t = __shfl_up_sync(0xffffffffu, incl, o);
            if (lane >= o) incl += t;
        }
        if (lane == 31) wsum[warp] = incl;
        __syncthreads();
        if (warp == 0) {
            int t = (lane < 16) ? wsum[lane] : 0;
            #pragma unroll
            for (int o = 1; o < 16; o <<= 1) {
                int u = __shfl_up_sync(0xffffffffu, t, o);
                if (lane >= o) t += u;
            }
            if (lane < 16) wsum[lane] = t;
        }
        __syncthreads();

        int pos   = (warp ? wsum[warp - 1] : 0) + (incl - local);
        int obase = b * NL;
        const int l = tid * 8;
        #pragma unroll
        for (int i = 0; i < 8; i++) {
            if (kbits & (1u << i)) g_order[obase + pos++] = l + i;
        }
        // No tail fill: stale entries are always valid ids; gather predicates
        // positions j >= cnt to 0.0f.

        __syncthreads();
        if (tid == 0) {
            g_count[b] = wsum[15];
            g_theta[b] = theta;
            __threadfence();                 // publish order/count before flag
            atomicExch(&g_ready[b], 1);
        }
    }

    // ---- Stage x-tile to SMEM (keeps DRAM busy during stats) ----
    const float4* xp = reinterpret_cast<const float4*>(x + base);
    #pragma unroll
    for (int i = 0; i < CPB * NL / 4 / GT; i++)
        reinterpret_cast<float4*>(sx)[tid + GT * i] = xp[tid + GT * i];

    // ---- Wait for OWN batch's stats only ----
    if (tid == 0) {
        while (*((volatile int*)&g_ready[b]) == 0) __nanosleep(32);
        __threadfence();                     // acquire
    }
    __syncthreads();                         // also covers staging

    // ---- Gather ----
    const int4* op = reinterpret_cast<const int4*>(g_order + b * NL);
    const int4 o0 = op[2 * tid];
    const int4 o1 = op[2 * tid + 1];
    const int  cnt = g_count[b];

    const int j = 8 * tid;
    #pragma unroll
    for (int r = 0; r < CPB; r++) {
        const float* sr = sx + r * NL;
        float4 r0, r1;
        r0.x = (j     < cnt) ? sr[o0.x] : 0.0f;
        r0.y = (j + 1 < cnt) ? sr[o0.y] : 0.0f;
        r0.z = (j + 2 < cnt) ? sr[o0.z] : 0.0f;
        r0.w = (j + 3 < cnt) ? sr[o0.w] : 0.0f;
        r1.x = (j + 4 < cnt) ? sr[o1.x] : 0.0f;
        r1.y = (j + 5 < cnt) ? sr[o1.y] : 0.0f;
        r1.z = (j + 6 < cnt) ? sr[o1.z] : 0.0f;
        r1.w = (j + 7 < cnt) ? sr[o1.w] : 0.0f;
        float4* yp = reinterpret_cast<float4*>(y + base + (size_t)r * NL) + 2 * tid;
        yp[0] = r0;
        yp[1] = r1;
    }

    // ---- Per-batch replay-safe reset: 96 arrivals per batch address ----
    if (tid == 0) {
        __threadfence();
        int d = atomicAdd(&g_bdone[b], 1);
        if (d == NCB - 1) {                  // last consumer of this batch
            atomicExch(&g_ready[b], 0);
            atomicExch(&g_bdone[b], 0);
        }
    }
}

// ---------------------------------------------------------------------------
// Scalars kernel (independent of fused kernel): recomputes per-batch theta &
// count from delta, last-arriving block reduces across batches. PDL secondary
// so it runs concurrently with the fused grid. 32 blocks x 256 threads.
// ---------------------------------------------------------------------------
__global__ __launch_bounds__(256) void scalars_kernel(const float* __restrict__ delta,
                                                      float* __restrict__ out_kr,
                                                      float* __restrict__ out_tm)
{
    const int b    = blockIdx.x;
    const int tid  = threadIdx.x;
    const int lane = tid & 31;
    const int warp = tid >> 5;   // 8 warps

    __shared__ float  smn[8], smx[8];
    __shared__ double ssum[8], ssq[8];
    __shared__ int    scnt[8];
    __shared__ float  s_lo, s_rng, s_theta;

    const float4* dp = reinterpret_cast<const float4*>(delta + (size_t)b * NL) + tid * 4;
    float a[16];
    #pragma unroll
    for (int i = 0; i < 4; i++) {
        float4 v = dp[i];
        a[4*i+0] = fabsf(v.x); a[4*i+1] = fabsf(v.y);
        a[4*i+2] = fabsf(v.z); a[4*i+3] = fabsf(v.w);
    }

    float mn = a[0], mx = a[0];
    double s0 = 0.0, s1 = 0.0, q0 = 0.0, q1 = 0.0;
    #pragma unroll
    for (int i = 0; i < 8; i++) {
        mn = fminf(mn, fminf(a[2*i], a[2*i+1]));
        mx = fmaxf(mx, fmaxf(a[2*i], a[2*i+1]));
        double d0 = (double)a[2*i], d1 = (double)a[2*i+1];
        s0 += d0; q0 += d0 * d0;
        s1 += d1; q1 += d1 * d1;
    }
    double s = s0 + s1, q = q0 + q1;

    #pragma unroll
    for (int o = 16; o; o >>= 1) {
        mn = fminf(mn, __shfl_xor_sync(0xffffffffu, mn, o));
        mx = fmaxf(mx, __shfl_xor_sync(0xffffffffu, mx, o));
        s += __shfl_xor_sync(0xffffffffu, s, o);
        q += __shfl_xor_sync(0xffffffffu, q, o);
    }
    if (lane == 0) { smn[warp] = mn; smx[warp] = mx; ssum[warp] = s; ssq[warp] = q; }
    __syncthreads();

    if (warp == 0) {
        mn = (lane < 8) ? smn[lane] :  1e30f;
        mx = (lane < 8) ? smx[lane] : -1e30f;
        s  = (lane < 8) ? ssum[lane] : 0.0;
        q  = (lane < 8) ? ssq[lane]  : 0.0;
        #pragma unroll
        for (int o = 4; o; o >>= 1) {
            mn = fminf(mn, __shfl_xor_sync(0xffffffffu, mn, o));
            mx = fmaxf(mx, __shfl_xor_sync(0xffffffffu, mx, o));
            s += __shfl_xor_sync(0xffffffffu, s, o);
            q += __shfl_xor_sync(0xffffffffu, q, o);
        }
        if (lane == 0) {
            float lo  = mn;
            float rng = fmaxf(mx - lo, 1e-3f);
            double mu_a  = s / (double)NL;
            double var_a = (q - s * s / (double)NL) / (double)(NL - 1);
            if (var_a < 0.0) var_a = 0.0;
            s_lo = lo; s_rng = rng;
            s_theta = (float)((mu_a - (double)lo) / (double)rng - 0.1 * sqrt(var_a) / (double)rng);
        }
    }
    __syncthreads();

    const float lo = s_lo, rng = s_rng, theta = s_theta;
    int local = 0;
    #pragma unroll
    for (int i = 0; i < 16; i++) {
        float imp = (a[i] - lo) / rng;
        local += (imp >= theta) ? 1 : 0;
    }
    #pragma unroll
    for (int o = 16; o; o >>= 1) local += __shfl_xor_sync(0xffffffffu, local, o);
    if (lane == 0) scnt[warp] = local;
    __syncthreads();

    if (tid == 0) {
        int cnt = 0;
        #pragma unroll
        for (int i = 0; i < 8; i++) cnt += scnt[i];
        g_scnt[b] = cnt;
        g_sth[b]  = theta;
        __threadfence();
        int t = atomicAdd(&g_sticket, 1);
        if (t == NB - 1) {
            __threadfence();
            float cs = 0.f, ts = 0.f;
            for (int i = 0; i < NB; i++) { cs += (float)g_scnt[i]; ts += g_sth[i]; }
            *out_kr = (cs / (float)NB) / (float)NL;
            *out_tm = ts / (float)NB;
            g_sticket = 0;   // reset for next replay
        }
    }
}

extern "C" void kernel_launch(void* const* d_in, const int* in_sizes, int n_in,
                              void* d_out, int out_size)
{
    const float* x     = (const float*)d_in[0];   // [32,192,64,64]
    const float* delta = (const float*)d_in[1];   // [32,1,64,64]
    float* out = (float*)d_out;

    fused_kernel<<<GBLK, GT>>>(x, delta, out);

    // Independent scalars kernel; PSS lets it overlap the fused grid's tail.
    cudaLaunchConfig_t cfg = {};
    cfg.gridDim  = dim3(NB, 1, 1);
    cfg.blockDim = dim3(256, 1, 1);
    cfg.dynamicSmemBytes = 0;
    cfg.stream = 0;
    cudaLaunchAttribute attr[1];
    attr[0].id = cudaLaunchAttributeProgrammaticStreamSerialization;
    attr[0].val.programmaticStreamSerializationAllowed = 1;
    cfg.attrs = attr;
    cfg.numAttrs = 1;
    cudaLaunchKernelEx(&cfg, scalars_kernel, delta,
                       out + (out_size - 2), out + (out_size - 1));
}

// round 17
// speedup vs baseline: 1.6375x; 1.6375x over previous
#include <cuda_runtime.h>
#include <cstdint>

#define NB  32
#define NC  192
#define NL  4096
#define CPB 2                  // channels per block
#define NCB (NC / CPB)         // 96 blocks per batch
#define GBLK (NB * NCB)        // 3072 blocks
#define GT  512                // threads per block

// Scratch (no dynamic allocation; zero-initialized at load)
__device__ int   g_order[NB * NL];   // always-valid token ids 0..NL-1
__device__ int   g_count[NB];
__device__ float g_theta[NB];
__device__ int   g_ready[NB];        // per-batch release flag  (reset per run)
__device__ int   g_bdone[NB];        // per-batch done tickets  (reset per run)
__device__ int   g_all;              // batch-complete ticket   (reset per run)

// ---------------------------------------------------------------------------
// Fused kernel.
//  * Blocks 0..NB-1 (guaranteed wave-1 resident) are producers: block p
//    computes stats + compaction order for batch p, publishes, releases
//    g_ready[p].
//  * Every block consumes for batch b = blk/NCB: stages its 32 KB x-tile
//    (DRAM busy during stats), spins ONLY on g_ready[b], gathers.
//  * Last consumer of each batch resets that batch's flags and arrives on
//    g_all; the 32nd arrival writes the two scalar outputs and resets g_all.
// ---------------------------------------------------------------------------
__global__ __launch_bounds__(GT, 4) void fused_kernel(const float* __restrict__ x,
                                                      const float* __restrict__ delta,
                                                      float* __restrict__ y,
                                                      float* __restrict__ out_kr,
                                                      float* __restrict__ out_tm)
{
    __shared__ float  sx[CPB * NL];          // 32 KB
    __shared__ float  smn[16], smx[16];
    __shared__ double ssum[16], ssq[16];
    __shared__ int    wsum[16];
    __shared__ float  s_lo, s_rng, s_theta;

    const int blk  = blockIdx.x;
    const int tid  = threadIdx.x;
    const int lane = tid & 31;
    const int warp = tid >> 5;               // 16 warps
    const int b    = blk / NCB;
    const int c0   = (blk % NCB) * CPB;
    const size_t base = ((size_t)b * NC + c0) * NL;

    // ---- Producer: blocks 0..NB-1 compute stats for batch p = blk ----
    if (blk < NB) {
        const int p = blk;
        const float4* dp = reinterpret_cast<const float4*>(delta + (size_t)p * NL) + tid * 2;
        float4 d0 = dp[0], d1 = dp[1];
        float a[8] = { fabsf(d0.x), fabsf(d0.y), fabsf(d0.z), fabsf(d0.w),
                       fabsf(d1.x), fabsf(d1.y), fabsf(d1.z), fabsf(d1.w) };

        float mn = a[0], mx = a[0];
        double s0 = 0.0, s1 = 0.0, q0 = 0.0, q1 = 0.0;
        #pragma unroll
        for (int i = 0; i < 4; i++) {
            mn = fminf(mn, fminf(a[2*i], a[2*i+1]));
            mx = fmaxf(mx, fmaxf(a[2*i], a[2*i+1]));
            double e0 = (double)a[2*i], e1 = (double)a[2*i+1];
            s0 += e0; q0 += e0 * e0;
            s1 += e1; q1 += e1 * e1;
        }
        double s = s0 + s1, q = q0 + q1;

        #pragma unroll
        for (int o = 16; o; o >>= 1) {
            mn = fminf(mn, __shfl_xor_sync(0xffffffffu, mn, o));
            mx = fmaxf(mx, __shfl_xor_sync(0xffffffffu, mx, o));
            s += __shfl_xor_sync(0xffffffffu, s, o);
            q += __shfl_xor_sync(0xffffffffu, q, o);
        }
        if (lane == 0) { smn[warp] = mn; smx[warp] = mx; ssum[warp] = s; ssq[warp] = q; }
        __syncthreads();

        if (warp == 0) {
            mn = (lane < 16) ? smn[lane] :  1e30f;
            mx = (lane < 16) ? smx[lane] : -1e30f;
            s  = (lane < 16) ? ssum[lane] : 0.0;
            q  = (lane < 16) ? ssq[lane]  : 0.0;
            #pragma unroll
            for (int o = 8; o; o >>= 1) {
                mn = fminf(mn, __shfl_xor_sync(0xffffffffu, mn, o));
                mx = fmaxf(mx, __shfl_xor_sync(0xffffffffu, mx, o));
                s += __shfl_xor_sync(0xffffffffu, s, o);
                q += __shfl_xor_sync(0xffffffffu, q, o);
            }
            if (lane == 0) {
                float lo  = mn;
                float rng = fmaxf(mx - lo, 1e-3f);
                double mu_a  = s / (double)NL;
                double var_a = (q - s * s / (double)NL) / (double)(NL - 1);
                if (var_a < 0.0) var_a = 0.0;
                s_lo = lo; s_rng = rng;
                s_theta = (float)((mu_a - (double)lo) / (double)rng
                                  - 0.1 * sqrt(var_a) / (double)rng);
            }
        }
        __syncthreads();

        const float lo = s_lo, rng = s_rng, theta = s_theta;
        unsigned kbits = 0;
        int local = 0;
        #pragma unroll
        for (int i = 0; i < 8; i++) {
            float imp = (a[i] - lo) / rng;
            if (imp >= theta) { kbits |= (1u << i); local++; }
        }

        int incl = local;
        #pragma unroll
        for (int o = 1; o < 32; o <<= 1) {
            int t = __shfl_up_sync(0xffffffffu, incl, o);
            if (lane >= o) incl += t;
        }
        if (lane == 31) wsum[warp] = incl;
        __syncthreads();
        if (warp == 0) {
            int t = (lane < 16) ? wsum[lane] : 0;
            #pragma unroll
            for (int o = 1; o < 16; o <<= 1) {
                int u = __shfl_up_sync(0xffffffffu, t, o);
                if (lane >= o) t += u;
            }
            if (lane < 16) wsum[lane] = t;
        }
        __syncthreads();

        int pos   = (warp ? wsum[warp - 1] : 0) + (incl - local);
        int obase = p * NL;
        const int l = tid * 8;
        #pragma unroll
        for (int i = 0; i < 8; i++) {
            if (kbits & (1u << i)) g_order[obase + pos++] = l + i;
        }
        // No tail fill: stale entries are always valid ids; gather predicates
        // positions j >= cnt to 0.0f.

        __syncthreads();
        if (tid == 0) {
            g_count[p] = wsum[15];
            g_theta[p] = theta;
            __threadfence();                 // publish before release
            atomicExch(&g_ready[p], 1);
        }
    }

    // ---- Stage x-tile to SMEM (keeps DRAM busy during stats) ----
    const float4* xp = reinterpret_cast<const float4*>(x + base);
    #pragma unroll
    for (int i = 0; i < CPB * NL / 4 / GT; i++)
        reinterpret_cast<float4*>(sx)[tid + GT * i] = xp[tid + GT * i];

    // ---- Wait for OWN batch's producer only (always wave-1 resident) ----
    if (tid == 0) {
        while (*((volatile int*)&g_ready[b]) == 0) __nanosleep(32);
        __threadfence();                     // acquire
    }
    __syncthreads();                         // also covers staging

    // ---- Gather ----
    const int4* op = reinterpret_cast<const int4*>(g_order + b * NL);
    const int4 o0 = op[2 * tid];
    const int4 o1 = op[2 * tid + 1];
    const int  cnt = g_count[b];

    const int j = 8 * tid;
    #pragma unroll
    for (int r = 0; r < CPB; r++) {
        const float* sr = sx + r * NL;
        float4 r0, r1;
        r0.x = (j     < cnt) ? sr[o0.x] : 0.0f;
        r0.y = (j + 1 < cnt) ? sr[o0.y] : 0.0f;
        r0.z = (j + 2 < cnt) ? sr[o0.z] : 0.0f;
        r0.w = (j + 3 < cnt) ? sr[o0.w] : 0.0f;
        r1.x = (j + 4 < cnt) ? sr[o1.x] : 0.0f;
        r1.y = (j + 5 < cnt) ? sr[o1.y] : 0.0f;
        r1.z = (j + 6 < cnt) ? sr[o1.z] : 0.0f;
        r1.w = (j + 7 < cnt) ? sr[o1.w] : 0.0f;
        float4* yp = reinterpret_cast<float4*>(y + base + (size_t)r * NL) + 2 * tid;
        yp[0] = r0;
        yp[1] = r1;
    }

    // ---- Per-batch reset + scalar emission by the global last batch ----
    if (tid == 0) {
        __threadfence();
        int d = atomicAdd(&g_bdone[b], 1);
        if (d == NCB - 1) {                  // last consumer of this batch
            atomicExch(&g_ready[b], 0);
            atomicExch(&g_bdone[b], 0);
            int t = atomicAdd(&g_all, 1);
            if (t == NB - 1) {               // all batches complete
                __threadfence();             // all g_count/g_theta visible
                float cs = 0.f, ts = 0.f;
                #pragma unroll 8
                for (int i = 0; i < NB; i++) { cs += (float)g_count[i]; ts += g_theta[i]; }
                *out_kr = (cs / (float)NB) / (float)NL;
                *out_tm = ts / (float)NB;
                atomicExch(&g_all, 0);       // reset for next replay
            }
        }
    }
}

extern "C" void kernel_launch(void* const* d_in, const int* in_sizes, int n_in,
                              void* d_out, int out_size)
{
    const float* x     = (const float*)d_in[0];   // [32,192,64,64]
    const float* delta = (const float*)d_in[1];   // [32,1,64,64]
    float* out = (float*)d_out;

    fused_kernel<<<GBLK, GT>>>(x, delta, out,
                               out + (out_size - 2), out + (out_size - 1));
}